// round 1
// baseline (speedup 1.0000x reference)
#include <cuda_runtime.h>
#include <cuda_bf16.h>
#include <math.h>

// Problem constants (fixed by reference setup_inputs)
#define BATCH 2
#define SEQ   2048
#define DIM   1024
#define HEADS 16
#define DHEAD 64
#define MROWS (BATCH * SEQ)   // 4096

// -------- device scratch (allocation-free rule: static __device__ arrays) ----
__device__ float g_q[MROWS * DIM];
__device__ float g_k[MROWS * DIM];
__device__ float g_v[MROWS * DIM];
__device__ float g_attn[MROWS * DIM];

// ============================================================================
// SGEMM: C[M,N] = scale * (A[M,K] @ B[N,K]^T) + bias[N] (bias optional)
// BM=BN=64, BK=16, 256 threads, 4x4 microtile per thread.
// ============================================================================
#define BM 64
#define BN 64
#define BK 16

__global__ __launch_bounds__(256)
void sgemm_nt(const float* __restrict__ A, const float* __restrict__ B,
              float* __restrict__ C, int M, int N, int K,
              float scale, const float* __restrict__ bias)
{
    __shared__ float As[BK][BM + 1];
    __shared__ float Bs[BK][BN + 1];

    const int tid = threadIdx.x;
    const int tx = tid & 15;          // 0..15 -> N micro
    const int ty = tid >> 4;          // 0..15 -> M micro
    const int row0 = blockIdx.y * BM;
    const int col0 = blockIdx.x * BN;

    const int lr = tid >> 2;          // 0..63 row within tile
    const int lc = (tid & 3) << 2;    // 0,4,8,12 col (float4)

    float acc[4][4];
#pragma unroll
    for (int i = 0; i < 4; i++)
#pragma unroll
        for (int j = 0; j < 4; j++) acc[i][j] = 0.f;

    for (int k0 = 0; k0 < K; k0 += BK) {
        float4 a4 = *(const float4*)(A + (size_t)(row0 + lr) * K + k0 + lc);
        float4 b4 = *(const float4*)(B + (size_t)(col0 + lr) * K + k0 + lc);
        As[lc + 0][lr] = a4.x; As[lc + 1][lr] = a4.y;
        As[lc + 2][lr] = a4.z; As[lc + 3][lr] = a4.w;
        Bs[lc + 0][lr] = b4.x; Bs[lc + 1][lr] = b4.y;
        Bs[lc + 2][lr] = b4.z; Bs[lc + 3][lr] = b4.w;
        __syncthreads();

#pragma unroll
        for (int k = 0; k < BK; k++) {
            float ra[4], rb[4];
#pragma unroll
            for (int i = 0; i < 4; i++) ra[i] = As[k][ty * 4 + i];
#pragma unroll
            for (int j = 0; j < 4; j++) rb[j] = Bs[k][tx * 4 + j];
#pragma unroll
            for (int i = 0; i < 4; i++)
#pragma unroll
                for (int j = 0; j < 4; j++)
                    acc[i][j] = fmaf(ra[i], rb[j], acc[i][j]);
        }
        __syncthreads();
    }

#pragma unroll
    for (int j = 0; j < 4; j++) {
        const int c = col0 + tx * 4 + j;
        const float bj = bias ? bias[c] : 0.f;
#pragma unroll
        for (int i = 0; i < 4; i++) {
            const int r = row0 + ty * 4 + i;
            C[(size_t)r * N + c] = acc[i][j] * scale + bj;
        }
    }
}

// ============================================================================
// Flash attention (fp32, online softmax). One block = 64 query rows of one
// (batch, head). 256 threads as 16x16, 4x4 microtiles.
// Dynamic smem: Qs, Ks, Vs, Ss each 64x65 floats = 66560 B.
// ============================================================================
#define ATT_PAD 65
#define ATT_SMEM (4 * 64 * ATT_PAD * 4)

__global__ __launch_bounds__(256)
void flash_attn(const float* __restrict__ Q, const float* __restrict__ K,
                const float* __restrict__ V, float* __restrict__ O)
{
    extern __shared__ float sm[];
    float* Qs = sm;
    float* Ks = Qs + 64 * ATT_PAD;
    float* Vs = Ks + 64 * ATT_PAD;
    float* Ss = Vs + 64 * ATT_PAD;

    const int b  = blockIdx.z;
    const int h  = blockIdx.y;
    const int q0 = blockIdx.x * 64;

    const float* Qb = Q + (size_t)b * SEQ * DIM + h * DHEAD;
    const float* Kb = K + (size_t)b * SEQ * DIM + h * DHEAD;
    const float* Vb = V + (size_t)b * SEQ * DIM + h * DHEAD;
    float*       Ob = O + (size_t)b * SEQ * DIM + h * DHEAD;

    const int tid = threadIdx.x;
    const int tx = tid & 15;
    const int ty = tid >> 4;

    // load Q tile [64 x 64]
    for (int idx = tid; idx < 64 * 16; idx += 256) {
        const int r  = idx >> 4;
        const int c4 = (idx & 15) << 2;
        float4 v4 = *(const float4*)(Qb + (size_t)(q0 + r) * DIM + c4);
        Qs[r * ATT_PAD + c4 + 0] = v4.x;
        Qs[r * ATT_PAD + c4 + 1] = v4.y;
        Qs[r * ATT_PAD + c4 + 2] = v4.z;
        Qs[r * ATT_PAD + c4 + 3] = v4.w;
    }

    float acc[4][4];
    float m_i[4], l_i[4];
#pragma unroll
    for (int i = 0; i < 4; i++) {
        m_i[i] = -INFINITY;
        l_i[i] = 0.f;
#pragma unroll
        for (int j = 0; j < 4; j++) acc[i][j] = 0.f;
    }
    __syncthreads();

    for (int k0 = 0; k0 < SEQ; k0 += 64) {
        // load K,V tiles
        for (int idx = tid; idx < 64 * 16; idx += 256) {
            const int r  = idx >> 4;
            const int c4 = (idx & 15) << 2;
            float4 kv = *(const float4*)(Kb + (size_t)(k0 + r) * DIM + c4);
            float4 vv = *(const float4*)(Vb + (size_t)(k0 + r) * DIM + c4);
            Ks[r * ATT_PAD + c4 + 0] = kv.x; Ks[r * ATT_PAD + c4 + 1] = kv.y;
            Ks[r * ATT_PAD + c4 + 2] = kv.z; Ks[r * ATT_PAD + c4 + 3] = kv.w;
            Vs[r * ATT_PAD + c4 + 0] = vv.x; Vs[r * ATT_PAD + c4 + 1] = vv.y;
            Vs[r * ATT_PAD + c4 + 2] = vv.z; Vs[r * ATT_PAD + c4 + 3] = vv.w;
        }
        __syncthreads();

        // S = Q @ K^T (64x64 tile), 4x4 per thread
        float s[4][4];
#pragma unroll
        for (int i = 0; i < 4; i++)
#pragma unroll
            for (int j = 0; j < 4; j++) s[i][j] = 0.f;

#pragma unroll 8
        for (int k = 0; k < 64; k++) {
            float rq[4], rk[4];
#pragma unroll
            for (int i = 0; i < 4; i++) rq[i] = Qs[(ty * 4 + i) * ATT_PAD + k];
#pragma unroll
            for (int j = 0; j < 4; j++) rk[j] = Ks[(tx * 4 + j) * ATT_PAD + k];
#pragma unroll
            for (int i = 0; i < 4; i++)
#pragma unroll
                for (int j = 0; j < 4; j++)
                    s[i][j] = fmaf(rq[i], rk[j], s[i][j]);
        }

        // online softmax per row (rows owned by tx-group of 16 threads)
#pragma unroll
        for (int i = 0; i < 4; i++) {
            float mx = fmaxf(fmaxf(s[i][0], s[i][1]), fmaxf(s[i][2], s[i][3]));
#pragma unroll
            for (int off = 8; off > 0; off >>= 1)
                mx = fmaxf(mx, __shfl_xor_sync(0xffffffffu, mx, off));
            const float m_new = fmaxf(m_i[i], mx);
            const float corr  = __expf(m_i[i] - m_new);
            float lsum = 0.f;
#pragma unroll
            for (int j = 0; j < 4; j++) {
                const float p = __expf(s[i][j] - m_new);
                Ss[(ty * 4 + i) * ATT_PAD + tx * 4 + j] = p;
                lsum += p;
            }
#pragma unroll
            for (int off = 8; off > 0; off >>= 1)
                lsum += __shfl_xor_sync(0xffffffffu, lsum, off);
            l_i[i] = l_i[i] * corr + lsum;
            m_i[i] = m_new;
#pragma unroll
            for (int j = 0; j < 4; j++) acc[i][j] *= corr;
        }
        __syncthreads();

        // acc += P @ V  (P in Ss, V in Vs)
#pragma unroll 8
        for (int c = 0; c < 64; c++) {
            float rp[4], rv[4];
#pragma unroll
            for (int i = 0; i < 4; i++) rp[i] = Ss[(ty * 4 + i) * ATT_PAD + c];
#pragma unroll
            for (int j = 0; j < 4; j++) rv[j] = Vs[c * ATT_PAD + tx * 4 + j];
#pragma unroll
            for (int i = 0; i < 4; i++)
#pragma unroll
                for (int j = 0; j < 4; j++)
                    acc[i][j] = fmaf(rp[i], rv[j], acc[i][j]);
        }
        __syncthreads();
    }

    // epilogue: normalize and store
#pragma unroll
    for (int i = 0; i < 4; i++) {
        const float inv = 1.f / l_i[i];
        const int r = q0 + ty * 4 + i;
#pragma unroll
        for (int j = 0; j < 4; j++)
            Ob[(size_t)r * DIM + tx * 4 + j] = acc[i][j] * inv;
    }
}

// ============================================================================
// kernel_launch
// ============================================================================
extern "C" void kernel_launch(void* const* d_in, const int* in_sizes, int n_in,
                              void* d_out, int out_size)
{
    const float* x   = (const float*)d_in[0];
    const float* Wq  = (const float*)d_in[1];
    const float* Wk  = (const float*)d_in[2];
    const float* Wv  = (const float*)d_in[3];
    const float* Wff = (const float*)d_in[4];
    const float* bff = (const float*)d_in[5];
    float* out = (float*)d_out;

    float *q, *k, *v, *attn;
    cudaGetSymbolAddress((void**)&q,    g_q);
    cudaGetSymbolAddress((void**)&k,    g_k);
    cudaGetSymbolAddress((void**)&v,    g_v);
    cudaGetSymbolAddress((void**)&attn, g_attn);

    cudaFuncSetAttribute(flash_attn, cudaFuncAttributeMaxDynamicSharedMemorySize,
                         ATT_SMEM);

    dim3 gemm_grid(DIM / BN, MROWS / BM);   // (16, 64)
    const float qscale = 1.0f / 32.0f;      // 1/sqrt(1024)

    sgemm_nt<<<gemm_grid, 256>>>(x, Wq, q, MROWS, DIM, DIM, qscale, nullptr);
    sgemm_nt<<<gemm_grid, 256>>>(x, Wk, k, MROWS, DIM, DIM, 1.0f, nullptr);
    sgemm_nt<<<gemm_grid, 256>>>(x, Wv, v, MROWS, DIM, DIM, 1.0f, nullptr);

    dim3 att_grid(SEQ / 64, HEADS, BATCH);  // (32, 16, 2)
    flash_attn<<<att_grid, 256, ATT_SMEM>>>(q, k, v, attn);

    sgemm_nt<<<gemm_grid, 256>>>(attn, Wff, out, MROWS, DIM, DIM, 1.0f, bff);
}

// round 2
// speedup vs baseline: 1.7115x; 1.7115x over previous
#include <cuda_runtime.h>
#include <cuda_bf16.h>
#include <math.h>
#include <stdint.h>

// Problem constants (fixed by reference setup_inputs)
#define BATCH 2
#define SEQ   2048
#define DIM   1024
#define HEADS 16
#define DHEAD 64
#define MROWS (BATCH * SEQ)   // 4096

// -------- device scratch (allocation-free rule: static __device__ arrays) ----
__device__ float g_q[MROWS * DIM];
__device__ float g_k[MROWS * DIM];
__device__ float g_v[MROWS * DIM];
__device__ float g_attn[MROWS * DIM];

// ============================================================================
// TF32 tensor-core GEMM: C[M,N] = scale * (A[M,K] @ B[N,K]^T) + bias[N]
// BM=128, BN=128, BK=32. 256 threads = 8 warps (4x2), warp tile 32x64.
// mma.sync.aligned.m16n8k8.row.col.f32.tf32.tf32.f32
// Smem stride 36 floats -> fragment-gather bank == lane (conflict-free).
// ============================================================================
#define GBM 128
#define GBN 128
#define GBK 32
#define GSTRIDE 36

__device__ __forceinline__ uint32_t f2tf32(float f) {
    uint32_t r;
    asm("cvt.rna.tf32.f32 %0, %1;" : "=r"(r) : "f"(f));
    return r;
}

__device__ __forceinline__ void mma_tf32(float c[4], const uint32_t a[4],
                                         const uint32_t b[2]) {
    asm volatile(
        "mma.sync.aligned.m16n8k8.row.col.f32.tf32.tf32.f32 "
        "{%0,%1,%2,%3}, {%4,%5,%6,%7}, {%8,%9}, {%0,%1,%2,%3};\n"
        : "+f"(c[0]), "+f"(c[1]), "+f"(c[2]), "+f"(c[3])
        : "r"(a[0]), "r"(a[1]), "r"(a[2]), "r"(a[3]),
          "r"(b[0]), "r"(b[1]));
}

__global__ __launch_bounds__(256)
void gemm_tf32(const float* __restrict__ A, const float* __restrict__ B,
               float* __restrict__ C, int M, int N, int K,
               float scale, const float* __restrict__ bias)
{
    __shared__ uint32_t As[GBM * GSTRIDE];
    __shared__ uint32_t Bs[GBN * GSTRIDE];

    const int tid  = threadIdx.x;
    const int lane = tid & 31;
    const int warp = tid >> 5;
    const int warp_m = warp >> 1;      // 0..3 -> 32-row slab
    const int warp_n = warp & 1;       // 0..1 -> 64-col slab
    const int row0 = blockIdx.y * GBM;
    const int col0 = blockIdx.x * GBN;

    // global->smem staging pattern: 32 rows x 8 float4-cols per pass, 4 passes
    const int ldr = tid >> 3;          // 0..31
    const int ldc = (tid & 7) << 2;    // 0,4,...,28

    float acc[2][8][4];
#pragma unroll
    for (int i = 0; i < 2; i++)
#pragma unroll
        for (int j = 0; j < 8; j++)
#pragma unroll
            for (int c = 0; c < 4; c++) acc[i][j][c] = 0.f;

    float4 pa[4], pb[4];

    // ---- load first tile ----
#pragma unroll
    for (int i = 0; i < 4; i++) {
        pa[i] = *(const float4*)(A + (size_t)(row0 + ldr + 32 * i) * K + ldc);
        pb[i] = *(const float4*)(B + (size_t)(col0 + ldr + 32 * i) * K + ldc);
    }
#pragma unroll
    for (int i = 0; i < 4; i++) {
        const int r = ldr + 32 * i;
        As[r * GSTRIDE + ldc + 0] = f2tf32(pa[i].x);
        As[r * GSTRIDE + ldc + 1] = f2tf32(pa[i].y);
        As[r * GSTRIDE + ldc + 2] = f2tf32(pa[i].z);
        As[r * GSTRIDE + ldc + 3] = f2tf32(pa[i].w);
        Bs[r * GSTRIDE + ldc + 0] = f2tf32(pb[i].x);
        Bs[r * GSTRIDE + ldc + 1] = f2tf32(pb[i].y);
        Bs[r * GSTRIDE + ldc + 2] = f2tf32(pb[i].z);
        Bs[r * GSTRIDE + ldc + 3] = f2tf32(pb[i].w);
    }
    __syncthreads();

    for (int k0 = 0; k0 < K; k0 += GBK) {
        // prefetch next tile into registers
        const bool has_next = (k0 + GBK) < K;
        if (has_next) {
#pragma unroll
            for (int i = 0; i < 4; i++) {
                pa[i] = *(const float4*)(A + (size_t)(row0 + ldr + 32 * i) * K + k0 + GBK + ldc);
                pb[i] = *(const float4*)(B + (size_t)(col0 + ldr + 32 * i) * K + k0 + GBK + ldc);
            }
        }

        // compute: 4 k-steps of 8
#pragma unroll
        for (int ks = 0; ks < 4; ks++) {
            const int kk = ks * 8 + (lane & 3);
            uint32_t afrag[2][4];
#pragma unroll
            for (int tm = 0; tm < 2; tm++) {
                const int r = warp_m * 32 + tm * 16 + (lane >> 2);
                afrag[tm][0] = As[r * GSTRIDE + kk];
                afrag[tm][1] = As[(r + 8) * GSTRIDE + kk];
                afrag[tm][2] = As[r * GSTRIDE + kk + 4];
                afrag[tm][3] = As[(r + 8) * GSTRIDE + kk + 4];
            }
            uint32_t bfrag[8][2];
#pragma unroll
            for (int tn = 0; tn < 8; tn++) {
                const int n = warp_n * 64 + tn * 8 + (lane >> 2);
                bfrag[tn][0] = Bs[n * GSTRIDE + kk];
                bfrag[tn][1] = Bs[n * GSTRIDE + kk + 4];
            }
#pragma unroll
            for (int tm = 0; tm < 2; tm++)
#pragma unroll
                for (int tn = 0; tn < 8; tn++)
                    mma_tf32(acc[tm][tn], afrag[tm], bfrag[tn]);
        }

        if (has_next) {
            __syncthreads();
#pragma unroll
            for (int i = 0; i < 4; i++) {
                const int r = ldr + 32 * i;
                As[r * GSTRIDE + ldc + 0] = f2tf32(pa[i].x);
                As[r * GSTRIDE + ldc + 1] = f2tf32(pa[i].y);
                As[r * GSTRIDE + ldc + 2] = f2tf32(pa[i].z);
                As[r * GSTRIDE + ldc + 3] = f2tf32(pa[i].w);
                Bs[r * GSTRIDE + ldc + 0] = f2tf32(pb[i].x);
                Bs[r * GSTRIDE + ldc + 1] = f2tf32(pb[i].y);
                Bs[r * GSTRIDE + ldc + 2] = f2tf32(pb[i].z);
                Bs[r * GSTRIDE + ldc + 3] = f2tf32(pb[i].w);
            }
            __syncthreads();
        }
    }

    // epilogue: C fragment layout m16n8: c0 (r, c), c1 (r, c+1), c2/c3 (+8 rows)
#pragma unroll
    for (int tm = 0; tm < 2; tm++) {
#pragma unroll
        for (int tn = 0; tn < 8; tn++) {
            const int r = row0 + warp_m * 32 + tm * 16 + (lane >> 2);
            const int c = col0 + warp_n * 64 + tn * 8 + ((lane & 3) << 1);
            const float b0 = bias ? bias[c]     : 0.f;
            const float b1 = bias ? bias[c + 1] : 0.f;
            float2 v0, v1;
            v0.x = acc[tm][tn][0] * scale + b0;
            v0.y = acc[tm][tn][1] * scale + b1;
            v1.x = acc[tm][tn][2] * scale + b0;
            v1.y = acc[tm][tn][3] * scale + b1;
            *(float2*)(C + (size_t)r * N + c)       = v0;
            *(float2*)(C + (size_t)(r + 8) * N + c) = v1;
        }
    }
}

// ============================================================================
// Flash attention (fp32, online softmax). One block = 64 query rows of one
// (batch, head). 256 threads as 16x16, 4x4 microtiles.
// ============================================================================
#define ATT_PAD 65
#define ATT_SMEM (4 * 64 * ATT_PAD * 4)

__global__ __launch_bounds__(256)
void flash_attn(const float* __restrict__ Q, const float* __restrict__ K,
                const float* __restrict__ V, float* __restrict__ O)
{
    extern __shared__ float sm[];
    float* Qs = sm;
    float* Ks = Qs + 64 * ATT_PAD;
    float* Vs = Ks + 64 * ATT_PAD;
    float* Ss = Vs + 64 * ATT_PAD;

    const int b  = blockIdx.z;
    const int h  = blockIdx.y;
    const int q0 = blockIdx.x * 64;

    const float* Qb = Q + (size_t)b * SEQ * DIM + h * DHEAD;
    const float* Kb = K + (size_t)b * SEQ * DIM + h * DHEAD;
    const float* Vb = V + (size_t)b * SEQ * DIM + h * DHEAD;
    float*       Ob = O + (size_t)b * SEQ * DIM + h * DHEAD;

    const int tid = threadIdx.x;
    const int tx = tid & 15;
    const int ty = tid >> 4;

    for (int idx = tid; idx < 64 * 16; idx += 256) {
        const int r  = idx >> 4;
        const int c4 = (idx & 15) << 2;
        float4 v4 = *(const float4*)(Qb + (size_t)(q0 + r) * DIM + c4);
        Qs[r * ATT_PAD + c4 + 0] = v4.x;
        Qs[r * ATT_PAD + c4 + 1] = v4.y;
        Qs[r * ATT_PAD + c4 + 2] = v4.z;
        Qs[r * ATT_PAD + c4 + 3] = v4.w;
    }

    float acc[4][4];
    float m_i[4], l_i[4];
#pragma unroll
    for (int i = 0; i < 4; i++) {
        m_i[i] = -INFINITY;
        l_i[i] = 0.f;
#pragma unroll
        for (int j = 0; j < 4; j++) acc[i][j] = 0.f;
    }
    __syncthreads();

    for (int k0 = 0; k0 < SEQ; k0 += 64) {
        for (int idx = tid; idx < 64 * 16; idx += 256) {
            const int r  = idx >> 4;
            const int c4 = (idx & 15) << 2;
            float4 kv = *(const float4*)(Kb + (size_t)(k0 + r) * DIM + c4);
            float4 vv = *(const float4*)(Vb + (size_t)(k0 + r) * DIM + c4);
            Ks[r * ATT_PAD + c4 + 0] = kv.x; Ks[r * ATT_PAD + c4 + 1] = kv.y;
            Ks[r * ATT_PAD + c4 + 2] = kv.z; Ks[r * ATT_PAD + c4 + 3] = kv.w;
            Vs[r * ATT_PAD + c4 + 0] = vv.x; Vs[r * ATT_PAD + c4 + 1] = vv.y;
            Vs[r * ATT_PAD + c4 + 2] = vv.z; Vs[r * ATT_PAD + c4 + 3] = vv.w;
        }
        __syncthreads();

        float s[4][4];
#pragma unroll
        for (int i = 0; i < 4; i++)
#pragma unroll
            for (int j = 0; j < 4; j++) s[i][j] = 0.f;

#pragma unroll 8
        for (int k = 0; k < 64; k++) {
            float rq[4], rk[4];
#pragma unroll
            for (int i = 0; i < 4; i++) rq[i] = Qs[(ty * 4 + i) * ATT_PAD + k];
#pragma unroll
            for (int j = 0; j < 4; j++) rk[j] = Ks[(tx * 4 + j) * ATT_PAD + k];
#pragma unroll
            for (int i = 0; i < 4; i++)
#pragma unroll
                for (int j = 0; j < 4; j++)
                    s[i][j] = fmaf(rq[i], rk[j], s[i][j]);
        }

#pragma unroll
        for (int i = 0; i < 4; i++) {
            float mx = fmaxf(fmaxf(s[i][0], s[i][1]), fmaxf(s[i][2], s[i][3]));
#pragma unroll
            for (int off = 8; off > 0; off >>= 1)
                mx = fmaxf(mx, __shfl_xor_sync(0xffffffffu, mx, off));
            const float m_new = fmaxf(m_i[i], mx);
            const float corr  = __expf(m_i[i] - m_new);
            float lsum = 0.f;
#pragma unroll
            for (int j = 0; j < 4; j++) {
                const float p = __expf(s[i][j] - m_new);
                Ss[(ty * 4 + i) * ATT_PAD + tx * 4 + j] = p;
                lsum += p;
            }
#pragma unroll
            for (int off = 8; off > 0; off >>= 1)
                lsum += __shfl_xor_sync(0xffffffffu, lsum, off);
            l_i[i] = l_i[i] * corr + lsum;
            m_i[i] = m_new;
#pragma unroll
            for (int j = 0; j < 4; j++) acc[i][j] *= corr;
        }
        __syncthreads();

#pragma unroll 8
        for (int c = 0; c < 64; c++) {
            float rp[4], rv[4];
#pragma unroll
            for (int i = 0; i < 4; i++) rp[i] = Ss[(ty * 4 + i) * ATT_PAD + c];
#pragma unroll
            for (int j = 0; j < 4; j++) rv[j] = Vs[c * ATT_PAD + tx * 4 + j];
#pragma unroll
            for (int i = 0; i < 4; i++)
#pragma unroll
                for (int j = 0; j < 4; j++)
                    acc[i][j] = fmaf(rp[i], rv[j], acc[i][j]);
        }
        __syncthreads();
    }

#pragma unroll
    for (int i = 0; i < 4; i++) {
        const float inv = 1.f / l_i[i];
        const int r = q0 + ty * 4 + i;
#pragma unroll
        for (int j = 0; j < 4; j++)
            Ob[(size_t)r * DIM + tx * 4 + j] = acc[i][j] * inv;
    }
}

// ============================================================================
// kernel_launch
// ============================================================================
extern "C" void kernel_launch(void* const* d_in, const int* in_sizes, int n_in,
                              void* d_out, int out_size)
{
    const float* x   = (const float*)d_in[0];
    const float* Wq  = (const float*)d_in[1];
    const float* Wk  = (const float*)d_in[2];
    const float* Wv  = (const float*)d_in[3];
    const float* Wff = (const float*)d_in[4];
    const float* bff = (const float*)d_in[5];
    float* out = (float*)d_out;

    float *q, *k, *v, *attn;
    cudaGetSymbolAddress((void**)&q,    g_q);
    cudaGetSymbolAddress((void**)&k,    g_k);
    cudaGetSymbolAddress((void**)&v,    g_v);
    cudaGetSymbolAddress((void**)&attn, g_attn);

    cudaFuncSetAttribute(flash_attn, cudaFuncAttributeMaxDynamicSharedMemorySize,
                         ATT_SMEM);

    dim3 gemm_grid(DIM / GBN, MROWS / GBM);   // (8, 32)
    const float qscale = 1.0f / 32.0f;        // 1/sqrt(1024)

    gemm_tf32<<<gemm_grid, 256>>>(x, Wq, q, MROWS, DIM, DIM, qscale, nullptr);
    gemm_tf32<<<gemm_grid, 256>>>(x, Wk, k, MROWS, DIM, DIM, 1.0f, nullptr);
    gemm_tf32<<<gemm_grid, 256>>>(x, Wv, v, MROWS, DIM, DIM, 1.0f, nullptr);

    dim3 att_grid(SEQ / 64, HEADS, BATCH);    // (32, 16, 2)
    flash_attn<<<att_grid, 256, ATT_SMEM>>>(q, k, v, attn);

    gemm_tf32<<<gemm_grid, 256>>>(attn, Wff, out, MROWS, DIM, DIM, 1.0f, bff);
}

// round 4
// speedup vs baseline: 3.6992x; 2.1614x over previous
#include <cuda_runtime.h>
#include <cuda_bf16.h>
#include <math.h>
#include <stdint.h>

// Problem constants (fixed by reference setup_inputs)
#define BATCH 2
#define SEQ   2048
#define DIM   1024
#define HEADS 16
#define DHEAD 64
#define MROWS (BATCH * SEQ)   // 4096

// -------- device scratch ----------------------------------------------------
__device__ float g_q[MROWS * DIM];
__device__ float g_k[MROWS * DIM];
__device__ float g_v[MROWS * DIM];
__device__ float g_attn[MROWS * DIM];

__device__ __forceinline__ uint32_t f2tf32(float f) {
    uint32_t r;
    asm("cvt.rna.tf32.f32 %0, %1;" : "=r"(r) : "f"(f));
    return r;
}

__device__ __forceinline__ void mma_tf32(float c[4], const uint32_t a[4],
                                         const uint32_t b[2]) {
    asm volatile(
        "mma.sync.aligned.m16n8k8.row.col.f32.tf32.tf32.f32 "
        "{%0,%1,%2,%3}, {%4,%5,%6,%7}, {%8,%9}, {%0,%1,%2,%3};\n"
        : "+f"(c[0]), "+f"(c[1]), "+f"(c[2]), "+f"(c[3])
        : "r"(a[0]), "r"(a[1]), "r"(a[2]), "r"(a[3]),
          "r"(b[0]), "r"(b[1]));
}

// ============================================================================
// TF32 tensor-core GEMM: C[M,N] = scale * (A[M,K] @ B[N,K]^T) + bias[N]
// ============================================================================
#define GBM 128
#define GBN 128
#define GBK 32
#define GSTRIDE 36

__global__ __launch_bounds__(256)
void gemm_tf32(const float* __restrict__ A, const float* __restrict__ B,
               float* __restrict__ C, int M, int N, int K,
               float scale, const float* __restrict__ bias)
{
    __shared__ uint32_t As[GBM * GSTRIDE];
    __shared__ uint32_t Bs[GBN * GSTRIDE];

    const int tid  = threadIdx.x;
    const int lane = tid & 31;
    const int warp = tid >> 5;
    const int warp_m = warp >> 1;
    const int warp_n = warp & 1;
    const int row0 = blockIdx.y * GBM;
    const int col0 = blockIdx.x * GBN;

    const int ldr = tid >> 3;
    const int ldc = (tid & 7) << 2;

    float acc[2][8][4];
#pragma unroll
    for (int i = 0; i < 2; i++)
#pragma unroll
        for (int j = 0; j < 8; j++)
#pragma unroll
            for (int c = 0; c < 4; c++) acc[i][j][c] = 0.f;

    float4 pa[4], pb[4];

#pragma unroll
    for (int i = 0; i < 4; i++) {
        pa[i] = *(const float4*)(A + (size_t)(row0 + ldr + 32 * i) * K + ldc);
        pb[i] = *(const float4*)(B + (size_t)(col0 + ldr + 32 * i) * K + ldc);
    }
#pragma unroll
    for (int i = 0; i < 4; i++) {
        const int r = ldr + 32 * i;
        As[r * GSTRIDE + ldc + 0] = f2tf32(pa[i].x);
        As[r * GSTRIDE + ldc + 1] = f2tf32(pa[i].y);
        As[r * GSTRIDE + ldc + 2] = f2tf32(pa[i].z);
        As[r * GSTRIDE + ldc + 3] = f2tf32(pa[i].w);
        Bs[r * GSTRIDE + ldc + 0] = f2tf32(pb[i].x);
        Bs[r * GSTRIDE + ldc + 1] = f2tf32(pb[i].y);
        Bs[r * GSTRIDE + ldc + 2] = f2tf32(pb[i].z);
        Bs[r * GSTRIDE + ldc + 3] = f2tf32(pb[i].w);
    }
    __syncthreads();

    for (int k0 = 0; k0 < K; k0 += GBK) {
        const bool has_next = (k0 + GBK) < K;
        if (has_next) {
#pragma unroll
            for (int i = 0; i < 4; i++) {
                pa[i] = *(const float4*)(A + (size_t)(row0 + ldr + 32 * i) * K + k0 + GBK + ldc);
                pb[i] = *(const float4*)(B + (size_t)(col0 + ldr + 32 * i) * K + k0 + GBK + ldc);
            }
        }

#pragma unroll
        for (int ks = 0; ks < 4; ks++) {
            const int kk = ks * 8 + (lane & 3);
            uint32_t afrag[2][4];
#pragma unroll
            for (int tm = 0; tm < 2; tm++) {
                const int r = warp_m * 32 + tm * 16 + (lane >> 2);
                afrag[tm][0] = As[r * GSTRIDE + kk];
                afrag[tm][1] = As[(r + 8) * GSTRIDE + kk];
                afrag[tm][2] = As[r * GSTRIDE + kk + 4];
                afrag[tm][3] = As[(r + 8) * GSTRIDE + kk + 4];
            }
            uint32_t bfrag[8][2];
#pragma unroll
            for (int tn = 0; tn < 8; tn++) {
                const int n = warp_n * 64 + tn * 8 + (lane >> 2);
                bfrag[tn][0] = Bs[n * GSTRIDE + kk];
                bfrag[tn][1] = Bs[n * GSTRIDE + kk + 4];
            }
#pragma unroll
            for (int tm = 0; tm < 2; tm++)
#pragma unroll
                for (int tn = 0; tn < 8; tn++)
                    mma_tf32(acc[tm][tn], afrag[tm], bfrag[tn]);
        }

        if (has_next) {
            __syncthreads();
#pragma unroll
            for (int i = 0; i < 4; i++) {
                const int r = ldr + 32 * i;
                As[r * GSTRIDE + ldc + 0] = f2tf32(pa[i].x);
                As[r * GSTRIDE + ldc + 1] = f2tf32(pa[i].y);
                As[r * GSTRIDE + ldc + 2] = f2tf32(pa[i].z);
                As[r * GSTRIDE + ldc + 3] = f2tf32(pa[i].w);
                Bs[r * GSTRIDE + ldc + 0] = f2tf32(pb[i].x);
                Bs[r * GSTRIDE + ldc + 1] = f2tf32(pb[i].y);
                Bs[r * GSTRIDE + ldc + 2] = f2tf32(pb[i].z);
                Bs[r * GSTRIDE + ldc + 3] = f2tf32(pb[i].w);
            }
            __syncthreads();
        }
    }

#pragma unroll
    for (int tm = 0; tm < 2; tm++) {
#pragma unroll
        for (int tn = 0; tn < 8; tn++) {
            const int r = row0 + warp_m * 32 + tm * 16 + (lane >> 2);
            const int c = col0 + warp_n * 64 + tn * 8 + ((lane & 3) << 1);
            const float b0 = bias ? bias[c]     : 0.f;
            const float b1 = bias ? bias[c + 1] : 0.f;
            float2 v0, v1;
            v0.x = acc[tm][tn][0] * scale + b0;
            v0.y = acc[tm][tn][1] * scale + b1;
            v1.x = acc[tm][tn][2] * scale + b0;
            v1.y = acc[tm][tn][3] * scale + b1;
            *(float2*)(C + (size_t)r * N + c)       = v0;
            *(float2*)(C + (size_t)(r + 8) * N + c) = v1;
        }
    }
}

// ============================================================================
// TF32 tensor-core flash attention.
// Block = 64 query rows of one (b,h). 128 threads = 4 warps, 16 rows/warp.
// Qs/Ps: stride 76 (A-style gather conflict-free)
// Ks/Vs: stride 72 (B-style gather conflict-free)
// Ps aliases Qs (Q hoisted to registers before main loop; warp-private rows).
// ============================================================================
#define ASTRIDE 76
#define BSTRIDE 72
#define FA_SMEM ((64 * ASTRIDE + 2 * 64 * BSTRIDE) * 4)

__global__ __launch_bounds__(128)
void flash_attn_tc(const float* __restrict__ Q, const float* __restrict__ K,
                   const float* __restrict__ V, float* __restrict__ O)
{
    extern __shared__ uint32_t usm[];
    uint32_t* Qs = usm;                      // 64 x ASTRIDE (aliased as Ps later)
    uint32_t* Ks = Qs + 64 * ASTRIDE;        // 64 x BSTRIDE
    uint32_t* Vs = Ks + 64 * BSTRIDE;        // 64 x BSTRIDE
    uint32_t* Ps = Qs;

    const int b  = blockIdx.z;
    const int h  = blockIdx.y;
    const int q0 = blockIdx.x * 64;

    const float* Qb = Q + (size_t)b * SEQ * DIM + h * DHEAD;
    const float* Kb = K + (size_t)b * SEQ * DIM + h * DHEAD;
    const float* Vb = V + (size_t)b * SEQ * DIM + h * DHEAD;
    float*       Ob = O + (size_t)b * SEQ * DIM + h * DHEAD;

    const int tid  = threadIdx.x;
    const int lane = tid & 31;
    const int warp = tid >> 5;          // 0..3 -> 16-row band
    const int g = lane >> 2;            // 0..7 group
    const int t = lane & 3;             // 0..3 thread-in-group
    const int wrow = warp * 16;

    // ---- load Q tile [64x64] -> Qs ----
    for (int it = 0; it < 8; it++) {
        const int idx = tid + it * 128;
        const int r  = idx >> 4;
        const int c4 = (idx & 15) << 2;
        float4 v4 = *(const float4*)(Qb + (size_t)(q0 + r) * DIM + c4);
        Qs[r * ASTRIDE + c4 + 0] = f2tf32(v4.x);
        Qs[r * ASTRIDE + c4 + 1] = f2tf32(v4.y);
        Qs[r * ASTRIDE + c4 + 2] = f2tf32(v4.z);
        Qs[r * ASTRIDE + c4 + 3] = f2tf32(v4.w);
    }
    __syncthreads();

    // ---- hoist Q fragments: qf[8 k-steps][4] ----
    uint32_t qf[8][4];
#pragma unroll
    for (int ks = 0; ks < 8; ks++) {
        const int kk = ks * 8 + t;
        qf[ks][0] = Qs[(wrow + g) * ASTRIDE + kk];
        qf[ks][1] = Qs[(wrow + g + 8) * ASTRIDE + kk];
        qf[ks][2] = Qs[(wrow + g) * ASTRIDE + kk + 4];
        qf[ks][3] = Qs[(wrow + g + 8) * ASTRIDE + kk + 4];
    }
    __syncthreads();   // everyone done reading Qs before it becomes Ps

    float oacc[8][4];
#pragma unroll
    for (int j = 0; j < 8; j++)
#pragma unroll
        for (int c = 0; c < 4; c++) oacc[j][c] = 0.f;
    float m_lo = -INFINITY, m_hi = -INFINITY;
    float l_lo = 0.f, l_hi = 0.f;

    for (int k0 = 0; k0 < SEQ; k0 += 64) {
        // ---- load K,V tiles [64x64] ----
        for (int it = 0; it < 8; it++) {
            const int idx = tid + it * 128;
            const int r  = idx >> 4;
            const int c4 = (idx & 15) << 2;
            float4 kv = *(const float4*)(Kb + (size_t)(k0 + r) * DIM + c4);
            float4 vv = *(const float4*)(Vb + (size_t)(k0 + r) * DIM + c4);
            Ks[r * BSTRIDE + c4 + 0] = f2tf32(kv.x);
            Ks[r * BSTRIDE + c4 + 1] = f2tf32(kv.y);
            Ks[r * BSTRIDE + c4 + 2] = f2tf32(kv.z);
            Ks[r * BSTRIDE + c4 + 3] = f2tf32(kv.w);
            Vs[r * BSTRIDE + c4 + 0] = f2tf32(vv.x);
            Vs[r * BSTRIDE + c4 + 1] = f2tf32(vv.y);
            Vs[r * BSTRIDE + c4 + 2] = f2tf32(vv.z);
            Vs[r * BSTRIDE + c4 + 3] = f2tf32(vv.w);
        }
        __syncthreads();

        // ---- S = Q @ K^T : sacc[8 n-tiles][4] ----
        float sacc[8][4];
#pragma unroll
        for (int j = 0; j < 8; j++)
#pragma unroll
            for (int c = 0; c < 4; c++) sacc[j][c] = 0.f;

#pragma unroll
        for (int ks = 0; ks < 8; ks++) {
            const int kk = ks * 8 + t;
            uint32_t bf[8][2];
#pragma unroll
            for (int j = 0; j < 8; j++) {
                bf[j][0] = Ks[(j * 8 + g) * BSTRIDE + kk];
                bf[j][1] = Ks[(j * 8 + g) * BSTRIDE + kk + 4];
            }
#pragma unroll
            for (int j = 0; j < 8; j++)
                mma_tf32(sacc[j], qf[ks], bf[j]);
        }

        // ---- online softmax (rows g and g+8 of this warp's band) ----
        float mx_lo = -INFINITY, mx_hi = -INFINITY;
#pragma unroll
        for (int j = 0; j < 8; j++) {
            mx_lo = fmaxf(mx_lo, fmaxf(sacc[j][0], sacc[j][1]));
            mx_hi = fmaxf(mx_hi, fmaxf(sacc[j][2], sacc[j][3]));
        }
        mx_lo = fmaxf(mx_lo, __shfl_xor_sync(0xffffffffu, mx_lo, 1));
        mx_lo = fmaxf(mx_lo, __shfl_xor_sync(0xffffffffu, mx_lo, 2));
        mx_hi = fmaxf(mx_hi, __shfl_xor_sync(0xffffffffu, mx_hi, 1));
        mx_hi = fmaxf(mx_hi, __shfl_xor_sync(0xffffffffu, mx_hi, 2));

        const float mnew_lo = fmaxf(m_lo, mx_lo);
        const float mnew_hi = fmaxf(m_hi, mx_hi);
        const float corr_lo = __expf(m_lo - mnew_lo);
        const float corr_hi = __expf(m_hi - mnew_hi);
        m_lo = mnew_lo; m_hi = mnew_hi;

        float sum_lo = 0.f, sum_hi = 0.f;
#pragma unroll
        for (int j = 0; j < 8; j++) {
            const float p0 = __expf(sacc[j][0] - mnew_lo);
            const float p1 = __expf(sacc[j][1] - mnew_lo);
            const float p2 = __expf(sacc[j][2] - mnew_hi);
            const float p3 = __expf(sacc[j][3] - mnew_hi);
            sum_lo += p0 + p1;
            sum_hi += p2 + p3;
            // store P to smem (tf32), C-fragment layout
            uint2 plo, phi;
            plo.x = f2tf32(p0); plo.y = f2tf32(p1);
            phi.x = f2tf32(p2); phi.y = f2tf32(p3);
            *(uint2*)(Ps + (wrow + g) * ASTRIDE + j * 8 + 2 * t)     = plo;
            *(uint2*)(Ps + (wrow + g + 8) * ASTRIDE + j * 8 + 2 * t) = phi;
        }
        sum_lo += __shfl_xor_sync(0xffffffffu, sum_lo, 1);
        sum_lo += __shfl_xor_sync(0xffffffffu, sum_lo, 2);
        sum_hi += __shfl_xor_sync(0xffffffffu, sum_hi, 1);
        sum_hi += __shfl_xor_sync(0xffffffffu, sum_hi, 2);
        l_lo = l_lo * corr_lo + sum_lo;
        l_hi = l_hi * corr_hi + sum_hi;

#pragma unroll
        for (int j = 0; j < 8; j++) {
            oacc[j][0] *= corr_lo; oacc[j][1] *= corr_lo;
            oacc[j][2] *= corr_hi; oacc[j][3] *= corr_hi;
        }
        __syncwarp();   // this warp's P rows written before reading

        // ---- O += P @ V ----
#pragma unroll
        for (int ks = 0; ks < 8; ks++) {
            const int kk = ks * 8 + t;
            uint32_t af[4];
            af[0] = Ps[(wrow + g) * ASTRIDE + kk];
            af[1] = Ps[(wrow + g + 8) * ASTRIDE + kk];
            af[2] = Ps[(wrow + g) * ASTRIDE + kk + 4];
            af[3] = Ps[(wrow + g + 8) * ASTRIDE + kk + 4];
            uint32_t bf[8][2];
#pragma unroll
            for (int j = 0; j < 8; j++) {
                bf[j][0] = Vs[(ks * 8 + t) * BSTRIDE + j * 8 + g];
                bf[j][1] = Vs[(ks * 8 + t + 4) * BSTRIDE + j * 8 + g];
            }
#pragma unroll
            for (int j = 0; j < 8; j++)
                mma_tf32(oacc[j], af, bf[j]);
        }
        __syncthreads();   // Ks/Vs reused next iteration
    }

    // ---- epilogue ----
    const float inv_lo = 1.f / l_lo;
    const float inv_hi = 1.f / l_hi;
    const int r_lo = q0 + wrow + g;
    const int r_hi = r_lo + 8;
#pragma unroll
    for (int j = 0; j < 8; j++) {
        const int c = j * 8 + 2 * t;
        float2 vlo, vhi;
        vlo.x = oacc[j][0] * inv_lo; vlo.y = oacc[j][1] * inv_lo;
        vhi.x = oacc[j][2] * inv_hi; vhi.y = oacc[j][3] * inv_hi;
        *(float2*)(Ob + (size_t)r_lo * DIM + c) = vlo;
        *(float2*)(Ob + (size_t)r_hi * DIM + c) = vhi;
    }
}

// ============================================================================
// kernel_launch
// ============================================================================
extern "C" void kernel_launch(void* const* d_in, const int* in_sizes, int n_in,
                              void* d_out, int out_size)
{
    const float* x   = (const float*)d_in[0];
    const float* Wq  = (const float*)d_in[1];
    const float* Wk  = (const float*)d_in[2];
    const float* Wv  = (const float*)d_in[3];
    const float* Wff = (const float*)d_in[4];
    const float* bff = (const float*)d_in[5];
    float* out = (float*)d_out;

    float *q, *k, *v, *attn;
    cudaGetSymbolAddress((void**)&q,    g_q);
    cudaGetSymbolAddress((void**)&k,    g_k);
    cudaGetSymbolAddress((void**)&v,    g_v);
    cudaGetSymbolAddress((void**)&attn, g_attn);

    cudaFuncSetAttribute(flash_attn_tc,
                         cudaFuncAttributeMaxDynamicSharedMemorySize, FA_SMEM);

    dim3 gemm_grid(DIM / GBN, MROWS / GBM);   // (8, 32)
    const float qscale = 1.0f / 32.0f;        // 1/sqrt(1024)

    gemm_tf32<<<gemm_grid, 256>>>(x, Wq, q, MROWS, DIM, DIM, qscale, nullptr);
    gemm_tf32<<<gemm_grid, 256>>>(x, Wk, k, MROWS, DIM, DIM, 1.0f, nullptr);
    gemm_tf32<<<gemm_grid, 256>>>(x, Wv, v, MROWS, DIM, DIM, 1.0f, nullptr);

    dim3 att_grid(SEQ / 64, HEADS, BATCH);    // (32, 16, 2)
    flash_attn_tc<<<att_grid, 128, FA_SMEM>>>(q, k, v, attn);

    gemm_tf32<<<gemm_grid, 256>>>(attn, Wff, out, MROWS, DIM, DIM, 1.0f, bff);
}